// round 3
// baseline (speedup 1.0000x reference)
#include <cuda_runtime.h>
#include <math.h>

#define HH 1024
#define WW 1024
#define PLANE (HH * WW)
#define KW 112   // padded kernel row width in smem (>= 2*RMAX+8 guard region)

// Scratch: pass1 output (transposed, [s][x][y]) and pass2 output ([s][y][x]).
__device__ float g_sc1[(size_t)52 * PLANE];
__device__ float g_sc2[(size_t)52 * PLANE];

// Pass-1 tap: fused multiply-add, single rounding (Eigen gebp / NEON vfma).
__device__ __forceinline__ float tap_fma(float acc, float k, float x)
{
    return __fmaf_rn(k, x, acc);
}
// Pass-2 tap: separate mul then add, two roundings (XLA naive loop emitter).
__device__ __forceinline__ float tap_muladd(float acc, float k, float x)
{
    return __fadd_rn(acc, __fmul_rn(k, x));
}

// ---------------------------------------------------------------------------
// Pass 1: vertical 1D conv of the single input image with ALL S kernels.
// Ascending-tap FMA chain, one accumulator per output (Eigen numerics).
// Output written transposed (g_sc1[s][x][y]) via smem staging transpose.
// ---------------------------------------------------------------------------
__global__ __launch_bounds__(256) void pass1_vert(
    const float* __restrict__ img, const float* __restrict__ k1,
    const float* __restrict__ sigmas, int S, int K, int RMAX)
{
    extern __shared__ float sm[];
    float* sk = sm;                        // S * KW
    float* simg = sk + S * KW;             // ROWS * 32
    const int ROWS = 64 + 2 * RMAX + 8;
    float* stage = simg + ROWS * 32;       // 64 * 33

    const int tid = threadIdx.x;
    const int tx = tid & 31, ty = tid >> 5;
    const int x0 = blockIdx.x * 32;
    const int y0 = blockIdx.y * 64;

    // Kernels into smem, zero-padded out to KW (protects the padded tap loop)
    for (int i = tid; i < S * KW; i += 256) {
        int s = i / KW, c = i - s * KW;
        sk[i] = (c < K) ? k1[s * K + c] : 0.0f;
    }
    // Image tile with max halo (shared across all sigmas); zero outside image
    for (int i = tid; i < ROWS * 32; i += 256) {
        int rr = i >> 5, cc = i & 31;
        int gy = y0 - RMAX + rr;
        simg[i] = ((unsigned)gy < HH) ? img[gy * WW + x0 + cc] : 0.0f;
    }
    __syncthreads();

    for (int s = 0; s < S; ++s) {
        float sg = sigmas[s];
        int r = (int)(5.0f * sg + 0.5f) + 1;   // +1 safety vs fp rounding of radius
        if (r > RMAX) r = RMAX;
        const int lenp = (2 * r + 8) & ~7;     // ceil((2r+1)/8)*8; extra taps hit k==0
        const float* kk = sk + s * KW + (RMAX - r);
        const int base = ty * 8 + (RMAX - r);

        float w[8], acc[8];
        #pragma unroll
        for (int j = 0; j < 8; ++j) { w[j] = simg[(base + j) * 32 + tx]; acc[j] = 0.0f; }
        for (int u = 0; u < lenp; u += 8) {
            #pragma unroll
            for (int uu = 0; uu < 8; ++uu) {
                float kv = kk[u + uu];
                #pragma unroll
                for (int j = 0; j < 8; ++j)
                    acc[j] = tap_fma(acc[j], kv, w[(uu + j) & 7]);
                w[uu] = simg[(base + u + uu + 8) * 32 + tx];
            }
        }
        __syncthreads();   // previous iteration's stage reads are done
        #pragma unroll
        for (int j = 0; j < 8; ++j) stage[(ty * 8 + j) * 33 + tx] = acc[j];
        __syncthreads();
        float* op = g_sc1 + (size_t)s * PLANE + (size_t)x0 * HH + y0;
        for (int e = tid; e < 2048; e += 256) {
            int xo = e >> 6, yo = e & 63;      // consecutive e -> consecutive yo: coalesced
            op[(size_t)xo * HH + yo] = stage[yo * 33 + xo];
        }
    }
}

// ---------------------------------------------------------------------------
// Pass 2: horizontal 1D conv = vertical conv on the transposed planes.
// Grouped conv in the reference -> naive emitter numerics: ascending taps,
// separate mul + add per tap, one accumulator.
// ---------------------------------------------------------------------------
__global__ __launch_bounds__(256) void pass2_horiz(
    const float* __restrict__ k1, const float* __restrict__ sigmas,
    int S, int K, int RMAX)
{
    __shared__ float sk[KW];
    __shared__ float stile[(64 + 2 * 50 + 8) * 32];
    __shared__ float stage[64 * 33];

    const int tid = threadIdx.x;
    const int tx = tid & 31, ty = tid >> 5;
    const int y0 = blockIdx.x * 32;   // minor dim of transposed layout
    const int x0 = blockIdx.y * 64;   // conv dim
    const int s = blockIdx.z;

    float sg = sigmas[s];
    int r = (int)(5.0f * sg + 0.5f) + 1;
    if (r > RMAX) r = RMAX;

    for (int i = tid; i < KW; i += 256) sk[i] = (i < K) ? k1[s * K + i] : 0.0f;

    const int ROWS = 64 + 2 * r + 8;
    const float* ip = g_sc1 + (size_t)s * PLANE;
    for (int i = tid; i < ROWS * 32; i += 256) {
        int rr = i >> 5, cc = i & 31;
        int gx = x0 - r + rr;
        stile[i] = ((unsigned)gx < WW) ? ip[(size_t)gx * HH + y0 + cc] : 0.0f;
    }
    __syncthreads();

    const float* kk = sk + (RMAX - r);
    const int base = ty * 8;
    const int lenp = (2 * r + 8) & ~7;

    float w[8], acc[8];
    #pragma unroll
    for (int j = 0; j < 8; ++j) { w[j] = stile[(base + j) * 32 + tx]; acc[j] = 0.0f; }
    for (int u = 0; u < lenp; u += 8) {
        #pragma unroll
        for (int uu = 0; uu < 8; ++uu) {
            float kv = kk[u + uu];
            #pragma unroll
            for (int j = 0; j < 8; ++j)
                acc[j] = tap_muladd(acc[j], kv, w[(uu + j) & 7]);
            w[uu] = stile[(base + u + uu + 8) * 32 + tx];
        }
    }
    #pragma unroll
    for (int j = 0; j < 8; ++j) stage[(ty * 8 + j) * 33 + tx] = acc[j];
    __syncthreads();
    float* op = g_sc2 + (size_t)s * PLANE + (size_t)y0 * WW + x0;
    for (int e = tid; e < 2048; e += 256) {
        int yo = e >> 6, xo = e & 63;         // consecutive e -> consecutive xo: coalesced
        op[(size_t)yo * WW + xo] = stage[xo * 33 + yo];
    }
}

// ---------------------------------------------------------------------------
// Pass 3: fused DoG + 3x3x3 maxpool (pad -inf) + mask, rolling over scale s.
// ---------------------------------------------------------------------------
__global__ __launch_bounds__(256) void pass3_dog_nms(
    const float* __restrict__ sigmas, float* __restrict__ out,
    int S, size_t out_n)
{
    __shared__ float gb[2][34 * 36];
    __shared__ float db[2][34 * 36];
    __shared__ float m2[3][1024];

    const int tid = threadIdx.x;
    const int x0 = blockIdx.x * 32 - 1;
    const int y0 = blockIdx.y * 32 - 1;
    const float NINF = -INFINITY;
    const size_t n1 = (size_t)(S - 1) * PLANE;

    for (int i = tid; i < 3 * 1024; i += 256) (&m2[0][0])[i] = NINF;

    for (int s = 0; s <= S; ++s) {
        if (s < S) {
            const float* gp = g_sc2 + (size_t)s * PLANE;
            for (int i = tid; i < 34 * 34; i += 256) {
                int yy = i / 34, xx = i - yy * 34;
                int gy = y0 + yy, gx = x0 + xx;
                gb[s & 1][yy * 36 + xx] =
                    ((unsigned)gy < HH && (unsigned)gx < WW) ? gp[gy * WW + gx] : 0.0f;
            }
        }
        __syncthreads();
        if (s >= 1 && s < S) {
            float sg = sigmas[s - 1];
            for (int i = tid; i < 34 * 34; i += 256) {
                int yy = i / 34, xx = i - yy * 34;
                int gy = y0 + yy, gx = x0 + xx;
                float v = NINF;  // -inf outside the image: matches maxpool padding
                if ((unsigned)gy < HH && (unsigned)gx < WW)
                    v = __fmul_rn(__fsub_rn(gb[(s - 1) & 1][yy * 36 + xx],
                                            gb[s & 1][yy * 36 + xx]), sg);
                db[(s - 1) & 1][yy * 36 + xx] = v;
            }
        } else if (s == S) {
            // flush: dog[S-1] doesn't exist; neutralize its (stale) m2 slot
            for (int i = tid; i < 1024; i += 256) m2[(S - 1) % 3][i] = NINF;
        }
        __syncthreads();
        if (s >= 1 && s < S) {
            int d = s - 1;
            const float* dp0 = &db[d & 1][0];
            for (int i = tid; i < 1024; i += 256) {
                int yy = i >> 5, xx = i & 31;
                const float* dp = dp0 + yy * 36 + xx;
                float m = fmaxf(fmaxf(dp[0], dp[1]), dp[2]);
                m = fmaxf(m, fmaxf(fmaxf(dp[36], dp[37]), dp[38]));
                m = fmaxf(m, fmaxf(fmaxf(dp[72], dp[73]), dp[74]));
                m2[d % 3][i] = m;
            }
        }
        __syncthreads();
        if (s >= 2) {
            int t = s - 2;
            for (int i = tid; i < 1024; i += 256) {
                int yy = i >> 5, xx = i & 31;
                float dv = db[t & 1][(yy + 1) * 36 + (xx + 1)];
                float p = fmaxf(fmaxf(m2[(t + 2) % 3][i], m2[t % 3][i]),
                                m2[(t + 1) % 3][i]);
                int gy = y0 + 1 + yy, gx = x0 + 1 + xx;
                size_t oidx = (size_t)t * PLANE + (size_t)gy * WW + gx;
                if (oidx < out_n) out[oidx] = dv;
                size_t midx = n1 + oidx;
                if (midx < out_n)
                    out[midx] = (dv == p && dv > 0.001f) ? 1.0f : 0.0f;
            }
        }
        __syncthreads();
    }
}

__global__ void zero_tail(float* p, size_t n)
{
    size_t i = (size_t)blockIdx.x * blockDim.x + threadIdx.x;
    if (i < n) p[i] = 0.0f;
}

extern "C" void kernel_launch(void* const* d_in, const int* in_sizes, int n_in,
                              void* d_out, int out_size)
{
    const float* img = (const float*)d_in[0];
    const float* k1  = (const float*)d_in[1];
    const float* sig = (const float*)d_in[2];
    int S = in_sizes[2];               // number of sigmas
    int K = in_sizes[1] / S;           // padded 1D kernel length
    int RMAX = (K - 1) / 2;
    float* out = (float*)d_out;
    size_t n1 = (size_t)(S - 1) * PLANE;
    size_t used = 2 * n1;
    size_t on = (size_t)out_size;

    size_t smem1 = ((size_t)S * KW + (size_t)(64 + 2 * RMAX + 8) * 32 + 64 * 33)
                   * sizeof(float);
    cudaFuncSetAttribute(pass1_vert, cudaFuncAttributeMaxDynamicSharedMemorySize,
                         (int)smem1);

    dim3 g1(WW / 32, HH / 64);
    pass1_vert<<<g1, 256, smem1>>>(img, k1, sig, S, K, RMAX);

    dim3 g2(HH / 32, WW / 64, S);
    pass2_horiz<<<g2, 256>>>(k1, sig, S, K, RMAX);

    dim3 g3(WW / 32, HH / 32);
    pass3_dog_nms<<<g3, 256>>>(sig, out, S, on);

    if (on > used) {
        size_t rem = on - used;
        int blocks = (int)((rem + 255) / 256);
        zero_tail<<<blocks, 256>>>(out + used, rem);
    }
}